// round 10
// baseline (speedup 1.0000x reference)
#include <cuda_runtime.h>
#include <cuda_bf16.h>

// EmbedGraphConv: out[n] = norm_r[n] * sum_{e: dst[e]=n} (embedding[feat[src[e]]] * norm_l[src[e]]) + bias
// Counting-sort edges by dst -> atomic-free aggregation.
// Hedged k_agg design: h stored bf16 (halves gather bytes, ALU-only shift/mask decode
// -- no F2F) AND loads are 16B LDG.128 per lane (same granularity as the fast fp32
// baseline): a half-warp covers one 256B bf16 row, each warp processes two edges at
// once, cross-half combine via 8x SHFL.XOR(16) per node.
// R9 resubmit: R8/R9 benches were broker timeouts, no signal obtained.

#define NN 50000
#define NE 800000
#define DD 128

// Scratch (device globals: allocation forbidden by harness rules)
__device__ int   g_out_deg[NN];
__device__ int   g_in_deg[NN];
__device__ int   g_offsets[NN];
__device__ int   g_cursor[NN];
__device__ int   g_sorted_src[NE];
__device__ uint2 g_h[(size_t)NN * (DD / 4)];   // 4 bf16 per uint2; 12.8 MB, L2-resident

__global__ void k_zero(int n) {
    int i = blockIdx.x * blockDim.x + threadIdx.x;
    if (i < n) { g_out_deg[i] = 0; g_in_deg[i] = 0; }
}

__global__ void k_hist(const int* __restrict__ src, const int* __restrict__ dst, int e) {
    int i = blockIdx.x * blockDim.x + threadIdx.x;
    if (i < e) {
        atomicAdd(&g_out_deg[src[i]], 1);
        atomicAdd(&g_in_deg[dst[i]], 1);
    }
}

// Exclusive scan of in_deg over NN bins: single block, 1024 threads, chunked.
// Writes both g_offsets (pristine, for k_agg) and g_cursor (consumed by scatter).
__global__ void k_scan(int n) {
    __shared__ int sh[1024];
    int t = threadIdx.x;
    int chunk = (n + 1023) / 1024;
    int lo = t * chunk;
    int hi = min(lo + chunk, n);
    int s = 0;
    for (int i = lo; i < hi; i++) s += g_in_deg[i];
    sh[t] = s;
    __syncthreads();
    for (int off = 1; off < 1024; off <<= 1) {
        int v = (t >= off) ? sh[t - off] : 0;
        __syncthreads();
        sh[t] += v;
        __syncthreads();
    }
    int run = (t == 0) ? 0 : sh[t - 1];
    for (int i = lo; i < hi; i++) {
        g_offsets[i] = run;
        g_cursor[i]  = run;
        run += g_in_deg[i];
    }
}

// Counting-sort scatter: cursor already holds base offset -> one atomic = final slot.
__global__ void k_scatter(const int* __restrict__ src, const int* __restrict__ dst, int e) {
    int i = blockIdx.x * blockDim.x + threadIdx.x;
    if (i < e) {
        int pos = atomicAdd(&g_cursor[dst[i]], 1);
        g_sorted_src[pos] = src[i];
    }
}

// Materialize h[n] = bf16(embedding[feat[n]] * out_deg[n]^{-1/2})
// One thread per float4 -> one 8B uint2 (4 bf16), round-to-nearest.
__global__ void k_build_h(const int* __restrict__ feat, const float4* __restrict__ emb, int n) {
    int idx = blockIdx.x * blockDim.x + threadIdx.x;
    if (idx < n * (DD / 4)) {
        int node = idx >> 5;
        int c    = idx & 31;
        float nl = rsqrtf((float)max(g_out_deg[node], 1));
        float4 v = emb[(size_t)feat[node] * 32 + c];
        __nv_bfloat162 a = __floats2bfloat162_rn(v.x * nl, v.y * nl);  // low half = v.x
        __nv_bfloat162 b = __floats2bfloat162_rn(v.z * nl, v.w * nl);
        uint2 u;
        u.x = *reinterpret_cast<unsigned int*>(&a);
        u.y = *reinterpret_cast<unsigned int*>(&b);
        g_h[idx] = u;
    }
}

// Warp-per-node aggregation, two edges in flight per warp:
// half-warp h (lanes 16h..16h+15) processes edges start+h, start+h+2, ...
// Each lane loads uint4 = 16B = 8 bf16 (LDG.128, same width as fp32 baseline).
// bf16 -> fp32 decode via shift/mask on the ALU pipe (no F2F).
__global__ void k_agg(const float4* __restrict__ bias4, float4* __restrict__ out4, int n) {
    int warp = (blockIdx.x * blockDim.x + threadIdx.x) >> 5;
    int lane = threadIdx.x & 31;
    if (warp >= n) return;

    int half = lane >> 4;        // 0 or 1
    int l16  = lane & 15;        // lane within half-warp; covers cols 8*l16 .. 8*l16+7
    int start = g_offsets[warp];
    int cnt   = g_in_deg[warp];
    const uint4* __restrict__ h4 = reinterpret_cast<const uint4*>(g_h);  // 16 uint4 per row

    float a0=0.f,a1=0.f,a2=0.f,a3=0.f,a4=0.f,a5=0.f,a6=0.f,a7=0.f;
    #define ACC(u) { \
        a0 += __uint_as_float((u).x << 16); a1 += __uint_as_float((u).x & 0xFFFF0000u); \
        a2 += __uint_as_float((u).y << 16); a3 += __uint_as_float((u).y & 0xFFFF0000u); \
        a4 += __uint_as_float((u).z << 16); a5 += __uint_as_float((u).z & 0xFFFF0000u); \
        a6 += __uint_as_float((u).w << 16); a7 += __uint_as_float((u).w & 0xFFFF0000u); }

    int i = half;
    // unroll-by-2 per half-warp: 4 edge-rows in flight per warp
    for (; i + 2 < cnt; i += 4) {
        int s0 = g_sorted_src[start + i];
        int s1 = g_sorted_src[start + i + 2];
        uint4 u0 = h4[(size_t)s0 * 16 + l16];
        uint4 u1 = h4[(size_t)s1 * 16 + l16];
        ACC(u0) ACC(u1)
    }
    for (; i < cnt; i += 2) {
        int s0 = g_sorted_src[start + i];
        uint4 u0 = h4[(size_t)s0 * 16 + l16];
        ACC(u0)
    }
    #undef ACC

    // Combine the two half-warps' partial sums (same columns live in lane l and l+16).
    a0 += __shfl_xor_sync(0xFFFFFFFFu, a0, 16);
    a1 += __shfl_xor_sync(0xFFFFFFFFu, a1, 16);
    a2 += __shfl_xor_sync(0xFFFFFFFFu, a2, 16);
    a3 += __shfl_xor_sync(0xFFFFFFFFu, a3, 16);
    a4 += __shfl_xor_sync(0xFFFFFFFFu, a4, 16);
    a5 += __shfl_xor_sync(0xFFFFFFFFu, a5, 16);
    a6 += __shfl_xor_sync(0xFFFFFFFFu, a6, 16);
    a7 += __shfl_xor_sync(0xFFFFFFFFu, a7, 16);

    if (half == 0) {
        float nr = rsqrtf((float)max(cnt, 1));
        float4 b0 = bias4[2 * l16];
        float4 b1 = bias4[2 * l16 + 1];
        float4 o0, o1;
        o0.x = a0 * nr + b0.x;  o0.y = a1 * nr + b0.y;
        o0.z = a2 * nr + b0.z;  o0.w = a3 * nr + b0.w;
        o1.x = a4 * nr + b1.x;  o1.y = a5 * nr + b1.y;
        o1.z = a6 * nr + b1.z;  o1.w = a7 * nr + b1.w;
        out4[(size_t)warp * 32 + 2 * l16]     = o0;
        out4[(size_t)warp * 32 + 2 * l16 + 1] = o1;
    }
}

extern "C" void kernel_launch(void* const* d_in, const int* in_sizes, int n_in,
                              void* d_out, int out_size) {
    const int*    feat = (const int*)d_in[0];
    const int*    src  = (const int*)d_in[1];
    const int*    dst  = (const int*)d_in[2];
    const float*  emb  = (const float*)d_in[3];
    const float*  bias = (const float*)d_in[4];
    float*        out  = (float*)d_out;

    int n = in_sizes[0];   // 50000
    int e = in_sizes[1];   // 800000

    const int T = 256;
    k_zero   <<<(n + T - 1) / T, T>>>(n);
    k_hist   <<<(e + T - 1) / T, T>>>(src, dst, e);
    k_scan   <<<1, 1024>>>(n);
    k_scatter<<<(e + T - 1) / T, T>>>(src, dst, e);
    k_build_h<<<(n * (DD / 4) + T - 1) / T, T>>>(feat, (const float4*)emb, n);
    k_agg    <<<(n * 32 + T - 1) / T, T>>>((const float4*)bias, (float4*)out, n);
}